// round 1
// baseline (speedup 1.0000x reference)
#include <cuda_runtime.h>

#define NN   200000
#define NE   400000
#define DIM  128
#define NL   5
#define NG   1000
#define ATOMV 119
#define BONDV 5

// ---------------- device scratch (no allocations allowed) ----------------
__device__ float g_h[NN * DIM];      // node features (ping)
__device__ float g_neigh[NN * DIM];  // scatter accumulator
__device__ float g_y[NN * DIM];      // post-GEMM, pre-BN
__device__ float g_deg[NN];          // degree, then reciprocal
__device__ float g_stats[2 * DIM];   // column sum / sumsq
__device__ float g_bnp[2 * DIM];     // BN scale / shift
__device__ float g_pool[NG * DIM];   // per-graph sums
__device__ float g_cnt[NG];          // per-graph node counts

__device__ __forceinline__ void red_add_v4(float* addr, float4 v) {
    asm volatile("red.global.add.v4.f32 [%0], {%1,%2,%3,%4};"
                 :: "l"(addr), "f"(v.x), "f"(v.y), "f"(v.z), "f"(v.w)
                 : "memory");
}

// ---------------- kernels ----------------

// h = atom_emb[nfeat]; deg = 1
__global__ void k_init(const int* __restrict__ nfeat,
                       const float* __restrict__ atom_emb) {
    int idx = blockIdx.x * blockDim.x + threadIdx.x;
    if (idx >= NN * 32) return;
    int node = idx >> 5, c = idx & 31;
    int a = nfeat[node];
    ((float4*)g_h)[node * 32 + c] = ((const float4*)atom_emb)[a * 32 + c];
    if (c == 0) g_deg[node] = 1.0f;
}

__global__ void k_deg(const int* __restrict__ dst) {
    int e = blockIdx.x * blockDim.x + threadIdx.x;
    if (e < NE) atomicAdd(&g_deg[dst[e]], 1.0f);
}

__global__ void k_recip() {
    int i = blockIdx.x * blockDim.x + threadIdx.x;
    if (i < NN) g_deg[i] = 1.0f / g_deg[i];
}

// zero neigh + stats
__global__ void k_zero() {
    int idx = blockIdx.x * blockDim.x + threadIdx.x;
    if (idx < NN * 32) ((float4*)g_neigh)[idx] = make_float4(0.f, 0.f, 0.f, 0.f);
    if (idx < 64) ((float4*)g_stats)[idx] = make_float4(0.f, 0.f, 0.f, 0.f);
}

// neigh[dst] += h[src] + edge_emb[l][efeat]   (one warp per edge; v4 reductions)
__global__ void k_scatter(const int* __restrict__ src, const int* __restrict__ dst,
                          const int* __restrict__ efeat,
                          const float* __restrict__ eembL) {
    int idx = blockIdx.x * blockDim.x + threadIdx.x;
    if (idx >= NE * 32) return;
    int e = idx >> 5, c = idx & 31;
    int s = src[e], d = dst[e], f = efeat[e];
    float4 hv = ((const float4*)g_h)[s * 32 + c];
    float4 ev = ((const float4*)eembL)[f * 32 + c];
    float4 m = make_float4(hv.x + ev.x, hv.y + ev.y, hv.z + ev.z, hv.w + ev.w);
    red_add_v4(&g_neigh[d * DIM + c * 4], m);
}

// y = ((h + neigh) * deg_inv) @ W + b ; accumulate column sum/sumsq into g_stats
__global__ void __launch_bounds__(256) k_gemm(const float* __restrict__ Wl,
                                              const float* __restrict__ bl) {
    __shared__ float As[8 * 128];
    __shared__ float Bs[8 * 128];
    __shared__ float ssum[DIM], ssq[DIM];

    int tid = threadIdx.x;
    if (tid < DIM) { ssum[tid] = 0.f; ssq[tid] = 0.f; }

    int rowBase = blockIdx.x * 128;
    int tx = tid & 15, ty = tid >> 4;

    float acc[8][8];
#pragma unroll
    for (int i = 0; i < 8; i++)
#pragma unroll
        for (int j = 0; j < 8; j++) acc[i][j] = 0.f;

    int arow = tid >> 1;            // 0..127
    int ak   = (tid & 1) << 2;      // 0 or 4
    int brow = tid >> 5;            // 0..7
    int bcol = (tid & 31) << 2;     // 0..124
    int grow = rowBase + arow;
    float dinv = (grow < NN) ? g_deg[grow] : 0.f;

    const float4* h4 = (const float4*)g_h;
    const float4* n4 = (const float4*)g_neigh;

    for (int k0 = 0; k0 < DIM; k0 += 8) {
        float4 av = make_float4(0.f, 0.f, 0.f, 0.f);
        if (grow < NN) {
            float4 hv = h4[grow * 32 + ((k0 + ak) >> 2)];
            float4 nv = n4[grow * 32 + ((k0 + ak) >> 2)];
            av.x = (hv.x + nv.x) * dinv;
            av.y = (hv.y + nv.y) * dinv;
            av.z = (hv.z + nv.z) * dinv;
            av.w = (hv.w + nv.w) * dinv;
        }
        As[(ak + 0) * 128 + arow] = av.x;
        As[(ak + 1) * 128 + arow] = av.y;
        As[(ak + 2) * 128 + arow] = av.z;
        As[(ak + 3) * 128 + arow] = av.w;
        *(float4*)&Bs[brow * 128 + bcol] =
            *(const float4*)&Wl[(k0 + brow) * 128 + bcol];
        __syncthreads();

#pragma unroll
        for (int kk = 0; kk < 8; kk++) {
            float4 a0 = *(float4*)&As[kk * 128 + ty * 8];
            float4 a1 = *(float4*)&As[kk * 128 + ty * 8 + 4];
            float4 b0 = *(float4*)&Bs[kk * 128 + tx * 8];
            float4 b1 = *(float4*)&Bs[kk * 128 + tx * 8 + 4];
            float a[8] = {a0.x, a0.y, a0.z, a0.w, a1.x, a1.y, a1.z, a1.w};
            float b[8] = {b0.x, b0.y, b0.z, b0.w, b1.x, b1.y, b1.z, b1.w};
#pragma unroll
            for (int i = 0; i < 8; i++)
#pragma unroll
                for (int j = 0; j < 8; j++)
                    acc[i][j] = fmaf(a[i], b[j], acc[i][j]);
        }
        __syncthreads();
    }

    float bias[8];
#pragma unroll
    for (int j = 0; j < 8; j++) bias[j] = bl[tx * 8 + j];

    float ls[8], lq[8];
#pragma unroll
    for (int j = 0; j < 8; j++) { ls[j] = 0.f; lq[j] = 0.f; }

#pragma unroll
    for (int i = 0; i < 8; i++) {
        int r = rowBase + ty * 8 + i;
        if (r < NN) {
            float yv[8];
#pragma unroll
            for (int j = 0; j < 8; j++) {
                yv[j] = acc[i][j] + bias[j];
                ls[j] += yv[j];
                lq[j] += yv[j] * yv[j];
            }
            float4* yo = (float4*)&g_y[r * DIM + tx * 8];
            yo[0] = make_float4(yv[0], yv[1], yv[2], yv[3]);
            yo[1] = make_float4(yv[4], yv[5], yv[6], yv[7]);
        }
    }
    __syncthreads();
#pragma unroll
    for (int j = 0; j < 8; j++) {
        atomicAdd(&ssum[tx * 8 + j], ls[j]);
        atomicAdd(&ssq[tx * 8 + j], lq[j]);
    }
    __syncthreads();
    if (tid < DIM) {
        atomicAdd(&g_stats[tid], ssum[tid]);
        atomicAdd(&g_stats[DIM + tid], ssq[tid]);
    }
}

// finalize BN affine params
__global__ void k_bnstat(const float* __restrict__ gammaL,
                         const float* __restrict__ betaL) {
    int t = threadIdx.x;  // 128
    float mu  = g_stats[t] * (1.0f / NN);
    float var = g_stats[DIM + t] * (1.0f / NN) - mu * mu;
    float rstd = rsqrtf(var + 1e-5f);
    float sc = rstd * gammaL[t];
    g_bnp[t] = sc;
    g_bnp[DIM + t] = betaL[t] - mu * sc;
}

// h = relu(y * scale + shift)
__global__ void k_bnrelu() {
    int idx = blockIdx.x * blockDim.x + threadIdx.x;
    if (idx >= NN * 32) return;
    int c = idx & 31;
    float4 y  = ((const float4*)g_y)[idx];
    float4 sc = ((const float4*)g_bnp)[c];
    float4 sh = ((const float4*)(g_bnp + DIM))[c];
    float4 r;
    r.x = fmaxf(fmaf(y.x, sc.x, sh.x), 0.f);
    r.y = fmaxf(fmaf(y.y, sc.y, sh.y), 0.f);
    r.z = fmaxf(fmaf(y.z, sc.z, sh.z), 0.f);
    r.w = fmaxf(fmaf(y.w, sc.w, sh.w), 0.f);
    ((float4*)g_h)[idx] = r;
}

__global__ void k_poolzero() {
    int idx = blockIdx.x * blockDim.x + threadIdx.x;
    if (idx < NG * 32) ((float4*)g_pool)[idx] = make_float4(0.f, 0.f, 0.f, 0.f);
    if (idx < NG) g_cnt[idx] = 0.f;
}

__global__ void k_pool(const int* __restrict__ n2g) {
    int idx = blockIdx.x * blockDim.x + threadIdx.x;
    if (idx >= NN * 32) return;
    int node = idx >> 5, c = idx & 31;
    int g = n2g[node];
    float4 hv = ((const float4*)g_h)[node * 32 + c];
    red_add_v4(&g_pool[g * DIM + c * 4], hv);
    if (c == 0) atomicAdd(&g_cnt[g], 1.0f);
}

// per-graph: out = relu(g @ W1 + b1) @ W2 + b2
__global__ void __launch_bounds__(128) k_mlp(const float* __restrict__ W1,
                                             const float* __restrict__ b1,
                                             const float* __restrict__ W2,
                                             const float* __restrict__ b2,
                                             float* __restrict__ out) {
    __shared__ float gs[DIM], ts[DIM];
    int gid = blockIdx.x, j = threadIdx.x;
    float cnt = fmaxf(g_cnt[gid], 1.0f);
    gs[j] = g_pool[gid * DIM + j] / cnt;
    __syncthreads();
    float acc = b1[j];
#pragma unroll 4
    for (int k = 0; k < DIM; k++) acc = fmaf(gs[k], W1[k * DIM + j], acc);
    ts[j] = fmaxf(acc, 0.f);
    __syncthreads();
    float acc2 = b2[j];
#pragma unroll 4
    for (int k = 0; k < DIM; k++) acc2 = fmaf(ts[k], W2[k * DIM + j], acc2);
    out[gid * DIM + j] = acc2;
}

// ---------------- launcher ----------------
extern "C" void kernel_launch(void* const* d_in, const int* in_sizes, int n_in,
                              void* d_out, int out_size) {
    const int*   nfeat    = (const int*)d_in[0];
    const int*   efeat    = (const int*)d_in[1];
    const int*   src      = (const int*)d_in[2];
    const int*   dst      = (const int*)d_in[3];
    const int*   n2g      = (const int*)d_in[4];
    const float* atom_emb = (const float*)d_in[5];
    const float* edge_emb = (const float*)d_in[6];
    const float* W        = (const float*)d_in[7];
    const float* b        = (const float*)d_in[8];
    const float* gamma    = (const float*)d_in[9];
    const float* beta     = (const float*)d_in[10];
    const float* W1       = (const float*)d_in[11];
    const float* b1       = (const float*)d_in[12];
    const float* W2       = (const float*)d_in[13];
    const float* b2       = (const float*)d_in[14];
    float* out = (float*)d_out;

    const int nthr = 256;
    int gNode32 = (NN * 32 + nthr - 1) / nthr;

    k_init<<<gNode32, nthr>>>(nfeat, atom_emb);
    k_deg<<<(NE + nthr - 1) / nthr, nthr>>>(dst);
    k_recip<<<(NN + nthr - 1) / nthr, nthr>>>();

    for (int l = 0; l < NL; l++) {
        k_zero<<<gNode32, nthr>>>();
        k_scatter<<<(NE * 32 + nthr - 1) / nthr, nthr>>>(
            src, dst, efeat, edge_emb + (size_t)l * BONDV * DIM);
        k_gemm<<<(NN + 127) / 128, 256>>>(W + (size_t)l * DIM * DIM,
                                          b + (size_t)l * DIM);
        k_bnstat<<<1, 128>>>(gamma + (size_t)l * DIM, beta + (size_t)l * DIM);
        k_bnrelu<<<gNode32, nthr>>>();
    }

    k_poolzero<<<(NG * 32 + nthr - 1) / nthr, nthr>>>();
    k_pool<<<gNode32, nthr>>>(n2g);
    k_mlp<<<NG, 128>>>(W1, b1, W2, b2, out);
}

// round 2
// speedup vs baseline: 1.1485x; 1.1485x over previous
#include <cuda_runtime.h>

#define NN   200000
#define NE   400000
#define DIM  128
#define NL   5
#define NG   1000
#define BONDV 5
#define NBLK 782   // ceil(NN/256)

// ---------------- device scratch ----------------
__device__ float g_h[NN * DIM];      // node features
__device__ float g_A[NN * DIM];      // normalized GEMM input
__device__ float g_y[NN * DIM];      // post-GEMM, pre-BN
__device__ float g_deg[NN];          // 1/(indeg+1)
__device__ float g_stats[2 * DIM];   // column sum / sumsq (self-rezeroing)
__device__ float g_bnp[2 * DIM];     // BN scale / shift
__device__ int   g_cnti[NN];         // in-degree counts
__device__ int   g_off[NN + 1];      // CSR offsets
__device__ int   g_cur[NN];          // fill cursors
__device__ int   g_blk[NBLK];        // scan block sums
__device__ int   g_edge[NE];         // packed (src<<3)|efeat

__device__ __forceinline__ unsigned long long pk2(float x, float y) {
    unsigned long long r;
    asm("mov.b64 %0, {%1, %2};" : "=l"(r) : "f"(x), "f"(y));
    return r;
}
__device__ __forceinline__ void upk2(unsigned long long v, float& x, float& y) {
    asm("mov.b64 {%0, %1}, %2;" : "=f"(x), "=f"(y) : "l"(v));
}
__device__ __forceinline__ void ffma2(unsigned long long& d,
                                      unsigned long long a,
                                      unsigned long long b) {
    asm("fma.rn.f32x2 %0, %1, %2, %0;" : "+l"(d) : "l"(a), "l"(b));
}

// ---------------- setup kernels ----------------

// h = atom_emb[nfeat]; zero in-degree counters
__global__ void k_init(const int* __restrict__ nfeat,
                       const float* __restrict__ atom_emb) {
    int idx = blockIdx.x * blockDim.x + threadIdx.x;
    if (idx >= NN * 32) return;
    int node = idx >> 5, c = idx & 31;
    int a = nfeat[node];
    ((float4*)g_h)[node * 32 + c] = ((const float4*)atom_emb)[a * 32 + c];
    if (c == 0) g_cnti[node] = 0;
}

__global__ void k_hist(const int* __restrict__ dst) {
    int e = blockIdx.x * blockDim.x + threadIdx.x;
    if (e < NE) atomicAdd(&g_cnti[dst[e]], 1);
}

// per-256-chunk exclusive scan; block totals to g_blk
__global__ void k_scan1() {
    __shared__ int s[256];
    int i = blockIdx.x * 256 + threadIdx.x;
    int c = (i < NN) ? g_cnti[i] : 0;
    s[threadIdx.x] = c;
    __syncthreads();
    int v = c;
#pragma unroll
    for (int d = 1; d < 256; d <<= 1) {
        int t = (threadIdx.x >= d) ? s[threadIdx.x - d] : 0;
        __syncthreads();
        v += t;
        s[threadIdx.x] = v;
        __syncthreads();
    }
    if (i < NN) g_off[i] = v - c;           // exclusive within chunk
    if (threadIdx.x == 255) g_blk[blockIdx.x] = v;
}

// exclusive scan of NBLK block totals (single block)
__global__ void k_scan2() {
    __shared__ int s[1024];
    int t = threadIdx.x;
    int c = (t < NBLK) ? g_blk[t] : 0;
    s[t] = c;
    __syncthreads();
    int v = c;
#pragma unroll
    for (int d = 1; d < 1024; d <<= 1) {
        int x = (t >= d) ? s[t - d] : 0;
        __syncthreads();
        v += x;
        s[t] = v;
        __syncthreads();
    }
    if (t < NBLK) g_blk[t] = v - c;
}

// finalize offsets, cursors, deg_inv
__global__ void k_scan3() {
    int i = blockIdx.x * blockDim.x + threadIdx.x;
    if (i >= NN) return;
    int off = g_off[i] + g_blk[i >> 8];
    g_off[i] = off;
    g_cur[i] = off;
    g_deg[i] = 1.0f / (float)(g_cnti[i] + 1);
    if (i == 0) g_off[NN] = NE;
}

__global__ void k_fill(const int* __restrict__ src, const int* __restrict__ dst,
                       const int* __restrict__ efeat) {
    int e = blockIdx.x * blockDim.x + threadIdx.x;
    if (e >= NE) return;
    int d = dst[e];
    int pos = atomicAdd(&g_cur[d], 1);
    g_edge[pos] = (src[e] << 3) | efeat[e];
}

// ---------------- per-layer kernels ----------------

// A[n] = (h[n] + sum_{e in in(n)} (h[src]+eemb[f])) * deg_inv[n]
// one warp per node, 4 floats per lane
__global__ void __launch_bounds__(256) k_aggregate(const float* __restrict__ eembL) {
    __shared__ float se[BONDV * DIM];
    int tid = threadIdx.x;
    if (tid < BONDV * 32)
        ((float4*)se)[tid] = ((const float4*)eembL)[tid];
    __syncthreads();

    int n = blockIdx.x * 8 + (tid >> 5);
    if (n >= NN) return;
    int c = tid & 31;

    const float4* h4 = (const float4*)g_h;
    const float4* se4 = (const float4*)se;

    float4 acc = h4[n * 32 + c];
    int p0 = g_off[n], p1 = g_off[n + 1];
    for (int p = p0; p < p1; p++) {
        int pk = g_edge[p];
        int s = pk >> 3, f = pk & 7;
        float4 hv = h4[s * 32 + c];
        float4 ev = se4[f * 32 + c];
        acc.x += hv.x + ev.x;
        acc.y += hv.y + ev.y;
        acc.z += hv.z + ev.z;
        acc.w += hv.w + ev.w;
    }
    float dinv = g_deg[n];
    acc.x *= dinv; acc.y *= dinv; acc.z *= dinv; acc.w *= dinv;
    ((float4*)g_A)[n * 32 + c] = acc;
}

// y = A @ W + b ; accumulate column sum/sumsq into g_stats (f32x2 FMAs)
__global__ void __launch_bounds__(256) k_gemm(const float* __restrict__ Wl,
                                              const float* __restrict__ bl) {
    __shared__ float As[8 * 128];
    __shared__ float Bs[8 * 128];
    __shared__ float ssum[DIM], ssq[DIM];

    int tid = threadIdx.x;
    if (tid < DIM) { ssum[tid] = 0.f; ssq[tid] = 0.f; }

    int rowBase = blockIdx.x * 128;
    int tx = tid & 15, ty = tid >> 4;

    unsigned long long acc2[8][4];
#pragma unroll
    for (int i = 0; i < 8; i++)
#pragma unroll
        for (int j = 0; j < 4; j++) acc2[i][j] = 0ULL;

    int arow = tid >> 1;
    int ak   = (tid & 1) << 2;
    int brow = tid >> 5;
    int bcol = (tid & 31) << 2;
    int grow = rowBase + arow;

    const float4* A4 = (const float4*)g_A;

    for (int k0 = 0; k0 < DIM; k0 += 8) {
        float4 av = make_float4(0.f, 0.f, 0.f, 0.f);
        if (grow < NN) av = A4[grow * 32 + ((k0 + ak) >> 2)];
        As[(ak + 0) * 128 + arow] = av.x;
        As[(ak + 1) * 128 + arow] = av.y;
        As[(ak + 2) * 128 + arow] = av.z;
        As[(ak + 3) * 128 + arow] = av.w;
        *(float4*)&Bs[brow * 128 + bcol] =
            *(const float4*)&Wl[(k0 + brow) * 128 + bcol];
        __syncthreads();

#pragma unroll
        for (int kk = 0; kk < 8; kk++) {
            float4 a0 = *(float4*)&As[kk * 128 + ty * 8];
            float4 a1 = *(float4*)&As[kk * 128 + ty * 8 + 4];
            float4 b0 = *(float4*)&Bs[kk * 128 + tx * 8];
            float4 b1 = *(float4*)&Bs[kk * 128 + tx * 8 + 4];
            float a[8] = {a0.x, a0.y, a0.z, a0.w, a1.x, a1.y, a1.z, a1.w};
            unsigned long long bp[4] = {pk2(b0.x, b0.y), pk2(b0.z, b0.w),
                                        pk2(b1.x, b1.y), pk2(b1.z, b1.w)};
#pragma unroll
            for (int i = 0; i < 8; i++) {
                unsigned long long ap = pk2(a[i], a[i]);
#pragma unroll
                for (int j = 0; j < 4; j++) ffma2(acc2[i][j], ap, bp[j]);
            }
        }
        __syncthreads();
    }

    float bias[8];
#pragma unroll
    for (int j = 0; j < 8; j++) bias[j] = bl[tx * 8 + j];

    float ls[8], lq[8];
#pragma unroll
    for (int j = 0; j < 8; j++) { ls[j] = 0.f; lq[j] = 0.f; }

#pragma unroll
    for (int i = 0; i < 8; i++) {
        int r = rowBase + ty * 8 + i;
        if (r < NN) {
            float yv[8];
#pragma unroll
            for (int j = 0; j < 4; j++)
                upk2(acc2[i][j], yv[2 * j], yv[2 * j + 1]);
#pragma unroll
            for (int j = 0; j < 8; j++) {
                yv[j] += bias[j];
                ls[j] += yv[j];
                lq[j] += yv[j] * yv[j];
            }
            float4* yo = (float4*)&g_y[r * DIM + tx * 8];
            yo[0] = make_float4(yv[0], yv[1], yv[2], yv[3]);
            yo[1] = make_float4(yv[4], yv[5], yv[6], yv[7]);
        }
    }
    __syncthreads();
#pragma unroll
    for (int j = 0; j < 8; j++) {
        atomicAdd(&ssum[tx * 8 + j], ls[j]);
        atomicAdd(&ssq[tx * 8 + j], lq[j]);
    }
    __syncthreads();
    if (tid < DIM) {
        atomicAdd(&g_stats[tid], ssum[tid]);
        atomicAdd(&g_stats[DIM + tid], ssq[tid]);
    }
}

// finalize BN params; re-zero stats for next layer (replay-safe)
__global__ void k_bnstat(const float* __restrict__ gammaL,
                         const float* __restrict__ betaL) {
    int t = threadIdx.x;  // 128
    float mu  = g_stats[t] * (1.0f / NN);
    float var = g_stats[DIM + t] * (1.0f / NN) - mu * mu;
    float rstd = rsqrtf(var + 1e-5f);
    float sc = rstd * gammaL[t];
    g_bnp[t] = sc;
    g_bnp[DIM + t] = betaL[t] - mu * sc;
    g_stats[t] = 0.f;
    g_stats[DIM + t] = 0.f;
}

// h = relu(y * scale + shift)
__global__ void k_bnrelu() {
    int idx = blockIdx.x * blockDim.x + threadIdx.x;
    if (idx >= NN * 32) return;
    int c = idx & 31;
    float4 y  = ((const float4*)g_y)[idx];
    float4 sc = ((const float4*)g_bnp)[c];
    float4 sh = ((const float4*)(g_bnp + DIM))[c];
    float4 r;
    r.x = fmaxf(fmaf(y.x, sc.x, sh.x), 0.f);
    r.y = fmaxf(fmaf(y.y, sc.y, sh.y), 0.f);
    r.z = fmaxf(fmaf(y.z, sc.z, sh.z), 0.f);
    r.w = fmaxf(fmaf(y.w, sc.w, sh.w), 0.f);
    ((float4*)g_h)[idx] = r;
}

// ---------------- fused pool + MLP (n2g is sorted) ----------------
__device__ __forceinline__ int lbound(const int* __restrict__ a, int n, int key) {
    int lo = 0, hi = n;
    while (lo < hi) {
        int mid = (lo + hi) >> 1;
        if (a[mid] < key) lo = mid + 1; else hi = mid;
    }
    return lo;
}

__global__ void __launch_bounds__(128) k_poolmlp(const int* __restrict__ n2g,
                                                 const float* __restrict__ W1,
                                                 const float* __restrict__ b1,
                                                 const float* __restrict__ W2,
                                                 const float* __restrict__ b2,
                                                 float* __restrict__ out) {
    __shared__ int range[2];
    __shared__ float gs[DIM], ts[DIM];
    int gid = blockIdx.x, t = threadIdx.x;
    if (t < 2) range[t] = lbound(n2g, NN, gid + t);
    __syncthreads();
    int s = range[0], e = range[1];

    float sum = 0.f;
    for (int n = s; n < e; n++) sum += g_h[n * DIM + t];
    float cnt = fmaxf((float)(e - s), 1.0f);
    gs[t] = sum / cnt;
    __syncthreads();

    float acc = b1[t];
#pragma unroll 4
    for (int k = 0; k < DIM; k++) acc = fmaf(gs[k], W1[k * DIM + t], acc);
    ts[t] = fmaxf(acc, 0.f);
    __syncthreads();
    float acc2 = b2[t];
#pragma unroll 4
    for (int k = 0; k < DIM; k++) acc2 = fmaf(ts[k], W2[k * DIM + t], acc2);
    out[gid * DIM + t] = acc2;
}

// ---------------- launcher ----------------
extern "C" void kernel_launch(void* const* d_in, const int* in_sizes, int n_in,
                              void* d_out, int out_size) {
    const int*   nfeat    = (const int*)d_in[0];
    const int*   efeat    = (const int*)d_in[1];
    const int*   src      = (const int*)d_in[2];
    const int*   dst      = (const int*)d_in[3];
    const int*   n2g      = (const int*)d_in[4];
    const float* atom_emb = (const float*)d_in[5];
    const float* edge_emb = (const float*)d_in[6];
    const float* W        = (const float*)d_in[7];
    const float* b        = (const float*)d_in[8];
    const float* gamma    = (const float*)d_in[9];
    const float* beta     = (const float*)d_in[10];
    const float* W1       = (const float*)d_in[11];
    const float* b1       = (const float*)d_in[12];
    const float* W2       = (const float*)d_in[13];
    const float* b2       = (const float*)d_in[14];
    float* out = (float*)d_out;

    const int nthr = 256;
    int gNode32 = (NN * 32 + nthr - 1) / nthr;
    int gEdge   = (NE + nthr - 1) / nthr;
    int gNode   = (NN + nthr - 1) / nthr;

    // setup: embeddings + CSR build
    k_init<<<gNode32, nthr>>>(nfeat, atom_emb);
    k_hist<<<gEdge, nthr>>>(dst);
    k_scan1<<<NBLK, 256>>>();
    k_scan2<<<1, 1024>>>();
    k_scan3<<<gNode, nthr>>>();
    k_fill<<<gEdge, nthr>>>(src, dst, efeat);

    for (int l = 0; l < NL; l++) {
        k_aggregate<<<(NN + 7) / 8, 256>>>(edge_emb + (size_t)l * BONDV * DIM);
        k_gemm<<<(NN + 127) / 128, 256>>>(W + (size_t)l * DIM * DIM,
                                          b + (size_t)l * DIM);
        k_bnstat<<<1, 128>>>(gamma + (size_t)l * DIM, beta + (size_t)l * DIM);
        k_bnrelu<<<gNode32, nthr>>>();
    }

    k_poolmlp<<<NG, 128>>>(n2g, W1, b1, W2, b2, out);
}

// round 3
// speedup vs baseline: 1.3097x; 1.1404x over previous
#include <cuda_runtime.h>

#define NN   200000
#define NE   400000
#define DIM  128
#define NL   5
#define NG   1000
#define BONDV 5
#define NBLK 782   // ceil(NN/256)

// ---------------- device scratch ----------------
__device__ float g_y[NN * DIM];      // layer output (pre-BN); also holds h0
__device__ float g_A[NN * DIM];      // normalized GEMM input
__device__ float g_deg[NN];          // 1/(indeg+1)
__device__ float g_stats[2 * DIM];   // column sum / sumsq (self-rezeroing)
__device__ float g_bnp[2 * DIM];     // BN scale / shift
__device__ int   g_cnti[NN];         // in-degree counts
__device__ int   g_off[NN + 1];      // CSR offsets
__device__ int   g_cur[NN];          // fill cursors
__device__ int   g_blk[NBLK];        // scan block sums
__device__ int   g_edge[NE];         // packed (src<<3)|efeat

__device__ __forceinline__ unsigned long long pk2(float x, float y) {
    unsigned long long r;
    asm("mov.b64 %0, {%1, %2};" : "=l"(r) : "f"(x), "f"(y));
    return r;
}
__device__ __forceinline__ void upk2(unsigned long long v, float& x, float& y) {
    asm("mov.b64 {%0, %1}, %2;" : "=f"(x), "=f"(y) : "l"(v));
}
__device__ __forceinline__ void ffma2(unsigned long long& d,
                                      unsigned long long a,
                                      unsigned long long b) {
    asm("fma.rn.f32x2 %0, %1, %2, %0;" : "+l"(d) : "l"(a), "l"(b));
}

// ---------------- setup kernels ----------------

// g_y = atom_emb[nfeat]; zero in-degree counters
__global__ void k_init(const int* __restrict__ nfeat,
                       const float* __restrict__ atom_emb) {
    int idx = blockIdx.x * blockDim.x + threadIdx.x;
    if (idx >= NN * 32) return;
    int node = idx >> 5, c = idx & 31;
    int a = nfeat[node];
    ((float4*)g_y)[node * 32 + c] = ((const float4*)atom_emb)[a * 32 + c];
    if (c == 0) g_cnti[node] = 0;
}

__global__ void k_hist(const int* __restrict__ dst) {
    int e = blockIdx.x * blockDim.x + threadIdx.x;
    if (e < NE) atomicAdd(&g_cnti[dst[e]], 1);
}

__global__ void k_scan1() {
    __shared__ int s[256];
    int i = blockIdx.x * 256 + threadIdx.x;
    int c = (i < NN) ? g_cnti[i] : 0;
    s[threadIdx.x] = c;
    __syncthreads();
    int v = c;
#pragma unroll
    for (int d = 1; d < 256; d <<= 1) {
        int t = (threadIdx.x >= d) ? s[threadIdx.x - d] : 0;
        __syncthreads();
        v += t;
        s[threadIdx.x] = v;
        __syncthreads();
    }
    if (i < NN) g_off[i] = v - c;
    if (threadIdx.x == 255) g_blk[blockIdx.x] = v;
}

__global__ void k_scan2() {
    __shared__ int s[1024];
    int t = threadIdx.x;
    int c = (t < NBLK) ? g_blk[t] : 0;
    s[t] = c;
    __syncthreads();
    int v = c;
#pragma unroll
    for (int d = 1; d < 1024; d <<= 1) {
        int x = (t >= d) ? s[t - d] : 0;
        __syncthreads();
        v += x;
        s[t] = v;
        __syncthreads();
    }
    if (t < NBLK) g_blk[t] = v - c;
}

__global__ void k_scan3() {
    int i = blockIdx.x * blockDim.x + threadIdx.x;
    if (i >= NN) return;
    int off = g_off[i] + g_blk[i >> 8];
    g_off[i] = off;
    g_cur[i] = off;
    g_deg[i] = 1.0f / (float)(g_cnti[i] + 1);
    if (i == 0) g_off[NN] = NE;
}

__global__ void k_fill(const int* __restrict__ src, const int* __restrict__ dst,
                       const int* __restrict__ efeat) {
    int e = blockIdx.x * blockDim.x + threadIdx.x;
    if (e >= NE) return;
    int d = dst[e];
    int pos = atomicAdd(&g_cur[d], 1);
    g_edge[pos] = (src[e] << 3) | efeat[e];
}

// ---------------- per-layer kernels ----------------

// h(n) = BN? relu(y[n]*sc+sh) : y[n]
// A[n] = (h[n] + sum_in (h[src]+eemb[f])) * deg_inv[n]
template <bool BN>
__global__ void __launch_bounds__(256) k_aggregate(const float* __restrict__ eembL) {
    __shared__ float se[BONDV * DIM];
    int tid = threadIdx.x;
    if (tid < BONDV * 32)
        ((float4*)se)[tid] = ((const float4*)eembL)[tid];
    __syncthreads();

    int n = blockIdx.x * 8 + (tid >> 5);
    if (n >= NN) return;
    int c = tid & 31;

    float4 sc, sh;
    if (BN) {
        sc = ((const float4*)g_bnp)[c];
        sh = ((const float4*)(g_bnp + DIM))[c];
    }

    const float4* y4 = (const float4*)g_y;
    const float4* se4 = (const float4*)se;

    float4 acc;
    {
        float4 v = y4[n * 32 + c];
        if (BN) {
            acc.x = fmaxf(fmaf(v.x, sc.x, sh.x), 0.f);
            acc.y = fmaxf(fmaf(v.y, sc.y, sh.y), 0.f);
            acc.z = fmaxf(fmaf(v.z, sc.z, sh.z), 0.f);
            acc.w = fmaxf(fmaf(v.w, sc.w, sh.w), 0.f);
        } else acc = v;
    }

    int p0 = g_off[n], p1 = g_off[n + 1];
    for (int p = p0; p < p1; p++) {
        int pk = g_edge[p];
        int s = pk >> 3, f = pk & 7;
        float4 v = y4[s * 32 + c];
        float4 ev = se4[f * 32 + c];
        if (BN) {
            acc.x += fmaxf(fmaf(v.x, sc.x, sh.x), 0.f) + ev.x;
            acc.y += fmaxf(fmaf(v.y, sc.y, sh.y), 0.f) + ev.y;
            acc.z += fmaxf(fmaf(v.z, sc.z, sh.z), 0.f) + ev.z;
            acc.w += fmaxf(fmaf(v.w, sc.w, sh.w), 0.f) + ev.w;
        } else {
            acc.x += v.x + ev.x;
            acc.y += v.y + ev.y;
            acc.z += v.z + ev.z;
            acc.w += v.w + ev.w;
        }
    }
    float dinv = g_deg[n];
    acc.x *= dinv; acc.y *= dinv; acc.z *= dinv; acc.w *= dinv;
    ((float4*)g_A)[n * 32 + c] = acc;
}

// y = A @ W + b ; accumulate column sum/sumsq into g_stats
// 128x128 tile, BK=16, double-buffered A & W staging, 1 sync per chunk
#define BK 16
#define ASTRIDE 132
__global__ void __launch_bounds__(256) k_gemm(const float* __restrict__ Wl,
                                              const float* __restrict__ bl) {
    __shared__ float As[2][BK * ASTRIDE];
    __shared__ float Ws[2][BK * DIM];
    __shared__ float ssum[DIM], ssq[DIM];

    int tid = threadIdx.x;
    if (tid < DIM) { ssum[tid] = 0.f; ssq[tid] = 0.f; }

    int rowBase = blockIdx.x * 128;
    int tx = tid & 15, ty = tid >> 4;

    // A stage mapping: 128 rows x 16 k per chunk
    int arow = tid >> 1;            // 0..127
    int ah   = tid & 1;             // k half (8 k each)
    int grow = rowBase + arow;
    // W stage mapping: 16 k-rows x 128 cols per chunk
    int wk = tid >> 4;              // 0..15
    int wc = (tid & 15) << 3;       // 0..120

    const float4* A4 = (const float4*)g_A;

    unsigned long long acc2[8][4];
#pragma unroll
    for (int i = 0; i < 8; i++)
#pragma unroll
        for (int j = 0; j < 4; j++) acc2[i][j] = 0ULL;

    float4 a0, a1, w0, w1;

    // prologue: load chunk 0
    a0 = make_float4(0.f, 0.f, 0.f, 0.f); a1 = a0;
    if (grow < NN) {
        a0 = A4[grow * 32 + ah * 2];
        a1 = A4[grow * 32 + ah * 2 + 1];
    }
    w0 = *(const float4*)&Wl[wk * DIM + wc];
    w1 = *(const float4*)&Wl[wk * DIM + wc + 4];
    {
        float av[8] = {a0.x, a0.y, a0.z, a0.w, a1.x, a1.y, a1.z, a1.w};
#pragma unroll
        for (int j = 0; j < 8; j++) As[0][(ah * 8 + j) * ASTRIDE + arow] = av[j];
        *(float4*)&Ws[0][wk * DIM + wc] = w0;
        *(float4*)&Ws[0][wk * DIM + wc + 4] = w1;
    }
    __syncthreads();

    for (int c = 0; c < DIM / BK; c++) {
        int cur = c & 1;
        // prefetch next chunk to registers
        if (c < DIM / BK - 1) {
            int k0 = (c + 1) * BK;
            a0 = make_float4(0.f, 0.f, 0.f, 0.f); a1 = a0;
            if (grow < NN) {
                a0 = A4[grow * 32 + (k0 >> 2) + ah * 2];
                a1 = A4[grow * 32 + (k0 >> 2) + ah * 2 + 1];
            }
            w0 = *(const float4*)&Wl[(k0 + wk) * DIM + wc];
            w1 = *(const float4*)&Wl[(k0 + wk) * DIM + wc + 4];
        }
        // compute current chunk
#pragma unroll
        for (int kk = 0; kk < BK; kk++) {
            float4 x0 = *(float4*)&As[cur][kk * ASTRIDE + ty * 8];
            float4 x1 = *(float4*)&As[cur][kk * ASTRIDE + ty * 8 + 4];
            float4 b0 = *(float4*)&Ws[cur][kk * DIM + tx * 8];
            float4 b1 = *(float4*)&Ws[cur][kk * DIM + tx * 8 + 4];
            float a[8] = {x0.x, x0.y, x0.z, x0.w, x1.x, x1.y, x1.z, x1.w};
            unsigned long long bp[4] = {pk2(b0.x, b0.y), pk2(b0.z, b0.w),
                                        pk2(b1.x, b1.y), pk2(b1.z, b1.w)};
#pragma unroll
            for (int i = 0; i < 8; i++) {
                unsigned long long ap = pk2(a[i], a[i]);
#pragma unroll
                for (int j = 0; j < 4; j++) ffma2(acc2[i][j], ap, bp[j]);
            }
        }
        // stage next chunk
        if (c < DIM / BK - 1) {
            int nxt = cur ^ 1;
            float av[8] = {a0.x, a0.y, a0.z, a0.w, a1.x, a1.y, a1.z, a1.w};
#pragma unroll
            for (int j = 0; j < 8; j++) As[nxt][(ah * 8 + j) * ASTRIDE + arow] = av[j];
            *(float4*)&Ws[nxt][wk * DIM + wc] = w0;
            *(float4*)&Ws[nxt][wk * DIM + wc + 4] = w1;
        }
        __syncthreads();
    }

    float bias[8];
#pragma unroll
    for (int j = 0; j < 8; j++) bias[j] = bl[tx * 8 + j];

    float ls[8], lq[8];
#pragma unroll
    for (int j = 0; j < 8; j++) { ls[j] = 0.f; lq[j] = 0.f; }

#pragma unroll
    for (int i = 0; i < 8; i++) {
        int r = rowBase + ty * 8 + i;
        if (r < NN) {
            float yv[8];
#pragma unroll
            for (int j = 0; j < 4; j++)
                upk2(acc2[i][j], yv[2 * j], yv[2 * j + 1]);
#pragma unroll
            for (int j = 0; j < 8; j++) {
                yv[j] += bias[j];
                ls[j] += yv[j];
                lq[j] += yv[j] * yv[j];
            }
            float4* yo = (float4*)&g_y[r * DIM + tx * 8];
            yo[0] = make_float4(yv[0], yv[1], yv[2], yv[3]);
            yo[1] = make_float4(yv[4], yv[5], yv[6], yv[7]);
        }
    }
    __syncthreads();
#pragma unroll
    for (int j = 0; j < 8; j++) {
        atomicAdd(&ssum[tx * 8 + j], ls[j]);
        atomicAdd(&ssq[tx * 8 + j], lq[j]);
    }
    __syncthreads();
    if (tid < DIM) {
        atomicAdd(&g_stats[tid], ssum[tid]);
        atomicAdd(&g_stats[DIM + tid], ssq[tid]);
    }
}

// finalize BN params; re-zero stats (replay-safe)
__global__ void k_bnstat(const float* __restrict__ gammaL,
                         const float* __restrict__ betaL) {
    int t = threadIdx.x;  // 128
    float mu  = g_stats[t] * (1.0f / NN);
    float var = g_stats[DIM + t] * (1.0f / NN) - mu * mu;
    float rstd = rsqrtf(var + 1e-5f);
    float sc = rstd * gammaL[t];
    g_bnp[t] = sc;
    g_bnp[DIM + t] = betaL[t] - mu * sc;
    g_stats[t] = 0.f;
    g_stats[DIM + t] = 0.f;
}

// ---------------- fused pool + MLP (n2g is sorted); applies final BN+relu ----
__device__ __forceinline__ int lbound(const int* __restrict__ a, int n, int key) {
    int lo = 0, hi = n;
    while (lo < hi) {
        int mid = (lo + hi) >> 1;
        if (a[mid] < key) lo = mid + 1; else hi = mid;
    }
    return lo;
}

__global__ void __launch_bounds__(128) k_poolmlp(const int* __restrict__ n2g,
                                                 const float* __restrict__ W1,
                                                 const float* __restrict__ b1,
                                                 const float* __restrict__ W2,
                                                 const float* __restrict__ b2,
                                                 float* __restrict__ out) {
    __shared__ int range[2];
    __shared__ float gs[DIM], ts[DIM];
    int gid = blockIdx.x, t = threadIdx.x;
    if (t < 2) range[t] = lbound(n2g, NN, gid + t);
    __syncthreads();
    int s = range[0], e = range[1];

    float sc = g_bnp[t], sh = g_bnp[DIM + t];
    float sum = 0.f;
    for (int n = s; n < e; n++)
        sum += fmaxf(fmaf(g_y[n * DIM + t], sc, sh), 0.f);
    float cnt = fmaxf((float)(e - s), 1.0f);
    gs[t] = sum / cnt;
    __syncthreads();

    float acc = b1[t];
#pragma unroll 4
    for (int k = 0; k < DIM; k++) acc = fmaf(gs[k], W1[k * DIM + t], acc);
    ts[t] = fmaxf(acc, 0.f);
    __syncthreads();
    float acc2 = b2[t];
#pragma unroll 4
    for (int k = 0; k < DIM; k++) acc2 = fmaf(ts[k], W2[k * DIM + t], acc2);
    out[gid * DIM + t] = acc2;
}

// ---------------- launcher ----------------
extern "C" void kernel_launch(void* const* d_in, const int* in_sizes, int n_in,
                              void* d_out, int out_size) {
    const int*   nfeat    = (const int*)d_in[0];
    const int*   efeat    = (const int*)d_in[1];
    const int*   src      = (const int*)d_in[2];
    const int*   dst      = (const int*)d_in[3];
    const int*   n2g      = (const int*)d_in[4];
    const float* atom_emb = (const float*)d_in[5];
    const float* edge_emb = (const float*)d_in[6];
    const float* W        = (const float*)d_in[7];
    const float* b        = (const float*)d_in[8];
    const float* gamma    = (const float*)d_in[9];
    const float* beta     = (const float*)d_in[10];
    const float* W1       = (const float*)d_in[11];
    const float* b1       = (const float*)d_in[12];
    const float* W2       = (const float*)d_in[13];
    const float* b2       = (const float*)d_in[14];
    float* out = (float*)d_out;

    const int nthr = 256;
    int gNode32 = (NN * 32 + nthr - 1) / nthr;
    int gEdge   = (NE + nthr - 1) / nthr;
    int gNode   = (NN + nthr - 1) / nthr;

    k_init<<<gNode32, nthr>>>(nfeat, atom_emb);
    k_hist<<<gEdge, nthr>>>(dst);
    k_scan1<<<NBLK, 256>>>();
    k_scan2<<<1, 1024>>>();
    k_scan3<<<gNode, nthr>>>();
    k_fill<<<gEdge, nthr>>>(src, dst, efeat);

    for (int l = 0; l < NL; l++) {
        if (l == 0)
            k_aggregate<false><<<(NN + 7) / 8, 256>>>(edge_emb);
        else
            k_aggregate<true><<<(NN + 7) / 8, 256>>>(edge_emb + (size_t)l * BONDV * DIM);
        k_gemm<<<(NN + 127) / 128, 256>>>(W + (size_t)l * DIM * DIM,
                                          b + (size_t)l * DIM);
        k_bnstat<<<1, 128>>>(gamma + (size_t)l * DIM, beta + (size_t)l * DIM);
    }

    k_poolmlp<<<NG, 128>>>(n2g, W1, b1, W2, b2, out);
}

// round 5
// speedup vs baseline: 1.7045x; 1.3014x over previous
#include <cuda_runtime.h>
#include <cuda_bf16.h>
#include <cstdint>

#define NN   200000
#define NE   400000
#define DIM  128
#define NL   5
#define NG   1000
#define BONDV 5
#define NBLK 782           // ceil(NN/256)
#define NTILE 1563         // ceil(NN/128)
#define ROW_BYTES 256      // 128 bf16 per row
#define IMG_BYTES ((size_t)NTILE * 128 * ROW_BYTES)

// ---------------- device scratch ----------------
__device__ float g_y[NN * DIM];       // layer output (pre-BN); also holds h0
__device__ float g_deg[NN];
__device__ float g_stats[2 * DIM];    // column sum / sumsq (self-rezeroing)
__device__ float g_bnp[2 * DIM];      // BN scale / shift
__device__ int   g_cnti[NN];
__device__ int   g_off[NN + 1];
__device__ int   g_cur[NN];
__device__ int   g_blk[NBLK];
__device__ int   g_edge[NE];          // packed (src<<3)|efeat
// bf16-split operands, row-major [row][k] bf16 (pad rows stay zero)
__device__ unsigned char g_ah[IMG_BYTES];
__device__ unsigned char g_al[IMG_BYTES];
__device__ unsigned char g_wh[NL * DIM * ROW_BYTES];  // W^T: [n][k]
__device__ unsigned char g_wl[NL * DIM * ROW_BYTES];

// bf16 hi/lo split of a float pair, packed (low half = first element)
__device__ __forceinline__ void bsplit(float a, float b, uint32_t& hi, uint32_t& lo) {
    __nv_bfloat162 h = __float22bfloat162_rn(make_float2(a, b));
    float2 hf = __bfloat1622float2(h);
    __nv_bfloat162 l = __float22bfloat162_rn(make_float2(a - hf.x, b - hf.y));
    hi = *(uint32_t*)&h;
    lo = *(uint32_t*)&l;
}

__device__ __forceinline__ uint32_t smem_u32(const void* p) {
    uint32_t a;
    asm("{ .reg .u64 t; cvta.to.shared.u64 t, %1; cvt.u32.u64 %0, t; }"
        : "=r"(a) : "l"(p));
    return a;
}
__device__ __forceinline__ void ldsm4(uint32_t& r0, uint32_t& r1, uint32_t& r2,
                                      uint32_t& r3, uint32_t addr) {
    asm volatile("ldmatrix.sync.aligned.m8n8.x4.shared.b16 {%0,%1,%2,%3}, [%4];"
                 : "=r"(r0), "=r"(r1), "=r"(r2), "=r"(r3) : "r"(addr));
}
__device__ __forceinline__ void mma16816(float* d, uint32_t a0, uint32_t a1,
                                         uint32_t a2, uint32_t a3,
                                         uint32_t b0, uint32_t b1) {
    asm volatile(
        "mma.sync.aligned.m16n8k16.row.col.f32.bf16.bf16.f32 "
        "{%0,%1,%2,%3}, {%4,%5,%6,%7}, {%8,%9}, {%0,%1,%2,%3};"
        : "+f"(d[0]), "+f"(d[1]), "+f"(d[2]), "+f"(d[3])
        : "r"(a0), "r"(a1), "r"(a2), "r"(a3), "r"(b0), "r"(b1));
}

// ---------------- setup kernels ----------------
__global__ void k_init(const int* __restrict__ nfeat,
                       const float* __restrict__ atom_emb) {
    int idx = blockIdx.x * blockDim.x + threadIdx.x;
    if (idx >= NN * 32) return;
    int node = idx >> 5, c = idx & 31;
    int a = nfeat[node];
    ((float4*)g_y)[node * 32 + c] = ((const float4*)atom_emb)[a * 32 + c];
    if (c == 0) g_cnti[node] = 0;
}

__global__ void k_hist(const int* __restrict__ dst) {
    int e = blockIdx.x * blockDim.x + threadIdx.x;
    if (e < NE) atomicAdd(&g_cnti[dst[e]], 1);
}

__global__ void k_scan1() {
    __shared__ int s[256];
    int i = blockIdx.x * 256 + threadIdx.x;
    int c = (i < NN) ? g_cnti[i] : 0;
    s[threadIdx.x] = c;
    __syncthreads();
    int v = c;
#pragma unroll
    for (int d = 1; d < 256; d <<= 1) {
        int t = (threadIdx.x >= d) ? s[threadIdx.x - d] : 0;
        __syncthreads();
        v += t;
        s[threadIdx.x] = v;
        __syncthreads();
    }
    if (i < NN) g_off[i] = v - c;
    if (threadIdx.x == 255) g_blk[blockIdx.x] = v;
}

__global__ void k_scan2() {
    __shared__ int s[1024];
    int t = threadIdx.x;
    int c = (t < NBLK) ? g_blk[t] : 0;
    s[t] = c;
    __syncthreads();
    int v = c;
#pragma unroll
    for (int d = 1; d < 1024; d <<= 1) {
        int x = (t >= d) ? s[t - d] : 0;
        __syncthreads();
        v += x;
        s[t] = v;
        __syncthreads();
    }
    if (t < NBLK) g_blk[t] = v - c;
}

__global__ void k_scan3() {
    int i = blockIdx.x * blockDim.x + threadIdx.x;
    if (i >= NN) return;
    int off = g_off[i] + g_blk[i >> 8];
    g_off[i] = off;
    g_cur[i] = off;
    g_deg[i] = 1.0f / (float)(g_cnti[i] + 1);
    if (i == 0) g_off[NN] = NE;
}

__global__ void k_fill(const int* __restrict__ src, const int* __restrict__ dst,
                       const int* __restrict__ efeat) {
    int e = blockIdx.x * blockDim.x + threadIdx.x;
    if (e >= NE) return;
    int d = dst[e];
    int pos = atomicAdd(&g_cur[d], 1);
    g_edge[pos] = (src[e] << 3) | efeat[e];
}

// W^T images: BT[n][k] = W[k][n], bf16 hi/lo row-major
__global__ void k_wconv(const float* __restrict__ W) {
    int l = blockIdx.x, t = threadIdx.x;  // t = n
    const float* Wl = W + (size_t)l * DIM * DIM;
    unsigned char* wh = g_wh + (size_t)l * DIM * ROW_BYTES;
    unsigned char* wl = g_wl + (size_t)l * DIM * ROW_BYTES;
    for (int k = 0; k < DIM; k += 2) {
        uint32_t hi, lo;
        bsplit(Wl[k * DIM + t], Wl[(k + 1) * DIM + t], hi, lo);
        uint32_t byte = (uint32_t)(t * ROW_BYTES + k * 2);
        *(uint32_t*)(wh + byte) = hi;
        *(uint32_t*)(wl + byte) = lo;
    }
}

// ---------------- per-layer kernels ----------------

// A row = (h[n] + sum_in (h[src]+eemb[f])) * deg_inv, h = BN? relu(y*sc+sh) : y
// output: bf16 hi/lo row-major
template <bool BN>
__global__ void __launch_bounds__(256) k_aggregate(const float* __restrict__ eembL) {
    __shared__ float se[BONDV * DIM];
    int tid = threadIdx.x;
    if (tid < BONDV * 32)
        ((float4*)se)[tid] = ((const float4*)eembL)[tid];
    __syncthreads();

    int n = blockIdx.x * 8 + (tid >> 5);
    if (n >= NN) return;
    int c = tid & 31;

    float4 sc, sh;
    if (BN) {
        sc = ((const float4*)g_bnp)[c];
        sh = ((const float4*)(g_bnp + DIM))[c];
    }

    const float4* y4 = (const float4*)g_y;
    const float4* se4 = (const float4*)se;

    float4 acc;
    {
        float4 v = y4[n * 32 + c];
        if (BN) {
            acc.x = fmaxf(fmaf(v.x, sc.x, sh.x), 0.f);
            acc.y = fmaxf(fmaf(v.y, sc.y, sh.y), 0.f);
            acc.z = fmaxf(fmaf(v.z, sc.z, sh.z), 0.f);
            acc.w = fmaxf(fmaf(v.w, sc.w, sh.w), 0.f);
        } else acc = v;
    }

    int p0 = g_off[n], p1 = g_off[n + 1];
    for (int p = p0; p < p1; p++) {
        int pk = g_edge[p];
        int s = pk >> 3, f = pk & 7;
        float4 v = y4[s * 32 + c];
        float4 ev = se4[f * 32 + c];
        if (BN) {
            acc.x += fmaxf(fmaf(v.x, sc.x, sh.x), 0.f) + ev.x;
            acc.y += fmaxf(fmaf(v.y, sc.y, sh.y), 0.f) + ev.y;
            acc.z += fmaxf(fmaf(v.z, sc.z, sh.z), 0.f) + ev.z;
            acc.w += fmaxf(fmaf(v.w, sc.w, sh.w), 0.f) + ev.w;
        } else {
            acc.x += v.x + ev.x;
            acc.y += v.y + ev.y;
            acc.z += v.z + ev.z;
            acc.w += v.w + ev.w;
        }
    }
    float dinv = g_deg[n];
    acc.x *= dinv; acc.y *= dinv; acc.z *= dinv; acc.w *= dinv;

    uint2 hi2, lo2;
    bsplit(acc.x, acc.y, hi2.x, lo2.x);
    bsplit(acc.z, acc.w, hi2.y, lo2.y);
    size_t base = (size_t)n * ROW_BYTES + c * 8;
    *(uint2*)(g_ah + base) = hi2;
    *(uint2*)(g_al + base) = lo2;
}

// ---- tensor-core GEMM via mma.sync bf16 3-term split: y = A@W + b + stats --
#define PITCH 272                 // smem row pitch (17 x 16B, conflict-free ldmatrix)
#define IMG_SM (128 * PITCH)      // 34816
#define SM_BIAS 0
#define SM_SUM  512
#define SM_SQ   1024
#define SM_AH   1536
#define SM_AL   (SM_AH + IMG_SM)
#define SM_WH   (SM_AL + IMG_SM)
#define SM_WL   (SM_WH + IMG_SM)
#define SM_TOTAL (SM_WL + IMG_SM)

__global__ void __launch_bounds__(256, 1) k_gemm(int layer, const float* __restrict__ bl) {
    extern __shared__ char smem[];
    uint32_t sb = smem_u32(smem);
    int tid = threadIdx.x, wid = tid >> 5, lane = tid & 31;
    int g = lane >> 2, tg = lane & 3;

    float* sbias = (float*)(smem + SM_BIAS);
    float* ssum  = (float*)(smem + SM_SUM);
    float* ssq   = (float*)(smem + SM_SQ);
    if (tid < 128) {
        sbias[tid] = bl[tid];
        ssum[tid] = 0.f;
        ssq[tid] = 0.f;
    }

    // stage: global row-major (256B rows) -> smem pitched (272B rows)
    {
        const float4* sa  = (const float4*)(g_ah + (size_t)blockIdx.x * 128 * ROW_BYTES);
        const float4* sl  = (const float4*)(g_al + (size_t)blockIdx.x * 128 * ROW_BYTES);
        const float4* swh = (const float4*)(g_wh + (size_t)layer * DIM * ROW_BYTES);
        const float4* swl = (const float4*)(g_wl + (size_t)layer * DIM * ROW_BYTES);
#pragma unroll
        for (int i = 0; i < 8; i++) {
            int idx = tid + i * 256;        // 2048 float4 per image
            int row = idx >> 4, q = idx & 15;
            int soff = row * (PITCH / 16) + q;
            ((float4*)(smem + SM_AH))[soff] = sa[idx];
            ((float4*)(smem + SM_AL))[soff] = sl[idx];
            ((float4*)(smem + SM_WH))[soff] = swh[idx];
            ((float4*)(smem + SM_WL))[soff] = swl[idx];
        }
    }
    __syncthreads();

    // per-lane ldmatrix address components
    // A (16x16 tile at rows R0=16*wid): row = R0 + (lane&15), koff = ks*32 + (lane>>4)*16
    uint32_t a_row = 16 * wid + (lane & 15);
    uint32_t a_kof = (lane >> 4) * 16;
    uint32_t ah_base = sb + SM_AH + a_row * PITCH + a_kof;
    uint32_t al_base = sb + SM_AL + a_row * PITCH + a_kof;
    // B (two 8-col tiles per x4): n = nt2*16 + ((lane>>4)<<3) + (lane&7),
    //                             koff = ks*32 + ((lane>>3)&1)*16
    uint32_t b_row = ((lane >> 4) << 3) + (lane & 7);
    uint32_t b_kof = ((lane >> 3) & 1) * 16;
    uint32_t wh_base = sb + SM_WH + b_row * PITCH + b_kof;
    uint32_t wl_base = sb + SM_WL + b_row * PITCH + b_kof;

    float d[16][4];
#pragma unroll
    for (int i = 0; i < 16; i++)
#pragma unroll
        for (int j = 0; j < 4; j++) d[i][j] = 0.f;

#pragma unroll
    for (int ks = 0; ks < 8; ks++) {
        uint32_t ah0, ah1, ah2, ah3, al0, al1, al2, al3;
        ldsm4(ah0, ah1, ah2, ah3, ah_base + ks * 32);
        ldsm4(al0, al1, al2, al3, al_base + ks * 32);
#pragma unroll
        for (int nt2 = 0; nt2 < 8; nt2++) {
            uint32_t bh0, bh1, bh2, bh3, bl0_, bl1_, bl2_, bl3_;
            uint32_t off = nt2 * 16 * PITCH + ks * 32;
            ldsm4(bh0, bh1, bh2, bh3, wh_base + off);
            ldsm4(bl0_, bl1_, bl2_, bl3_, wl_base + off);
            // n-tile 2*nt2
            mma16816(d[2 * nt2], ah0, ah1, ah2, ah3, bh0, bh1);
            mma16816(d[2 * nt2], al0, al1, al2, al3, bh0, bh1);
            mma16816(d[2 * nt2], ah0, ah1, ah2, ah3, bl0_, bl1_);
            // n-tile 2*nt2+1
            mma16816(d[2 * nt2 + 1], ah0, ah1, ah2, ah3, bh2, bh3);
            mma16816(d[2 * nt2 + 1], al0, al1, al2, al3, bh2, bh3);
            mma16816(d[2 * nt2 + 1], ah0, ah1, ah2, ah3, bl2_, bl3_);
        }
    }

    // epilogue: bias, masked store, column stats
    int row0 = blockIdx.x * 128 + 16 * wid + g;
    int row1 = row0 + 8;
    bool v0 = row0 < NN, v1 = row1 < NN;

#pragma unroll
    for (int nt = 0; nt < 16; nt++) {
        int c0 = nt * 8 + 2 * tg;
        float b0 = sbias[c0], b1 = sbias[c0 + 1];
        float y0 = d[nt][0] + b0, y1 = d[nt][1] + b1;
        float y2 = d[nt][2] + b0, y3 = d[nt][3] + b1;
        if (!v0) { y0 = 0.f; y1 = 0.f; }
        if (!v1) { y2 = 0.f; y3 = 0.f; }
        if (v0) *(float2*)&g_y[(size_t)row0 * DIM + c0] = make_float2(y0, y1);
        if (v1) *(float2*)&g_y[(size_t)row1 * DIM + c0] = make_float2(y2, y3);

        float s0 = y0 + y2, s1 = y1 + y3;
        float q0 = y0 * y0 + y2 * y2, q1 = y1 * y1 + y3 * y3;
#pragma unroll
        for (int m = 4; m <= 16; m <<= 1) {
            s0 += __shfl_xor_sync(0xffffffffu, s0, m);
            s1 += __shfl_xor_sync(0xffffffffu, s1, m);
            q0 += __shfl_xor_sync(0xffffffffu, q0, m);
            q1 += __shfl_xor_sync(0xffffffffu, q1, m);
        }
        if (lane < 4) {
            atomicAdd(&ssum[c0], s0);
            atomicAdd(&ssum[c0 + 1], s1);
            atomicAdd(&ssq[c0], q0);
            atomicAdd(&ssq[c0 + 1], q1);
        }
    }
    __syncthreads();
    if (tid < 128) {
        atomicAdd(&g_stats[tid], ssum[tid]);
        atomicAdd(&g_stats[DIM + tid], ssq[tid]);
    }
}

// finalize BN params; re-zero stats (replay-safe)
__global__ void k_bnstat(const float* __restrict__ gammaL,
                         const float* __restrict__ betaL) {
    int t = threadIdx.x;  // 128
    float mu  = g_stats[t] * (1.0f / NN);
    float var = g_stats[DIM + t] * (1.0f / NN) - mu * mu;
    float rstd = rsqrtf(var + 1e-5f);
    float sc = rstd * gammaL[t];
    g_bnp[t] = sc;
    g_bnp[DIM + t] = betaL[t] - mu * sc;
    g_stats[t] = 0.f;
    g_stats[DIM + t] = 0.f;
}

// ---------------- fused pool + MLP (n2g sorted); applies final BN+relu ------
__device__ __forceinline__ int lbound(const int* __restrict__ a, int n, int key) {
    int lo = 0, hi = n;
    while (lo < hi) {
        int mid = (lo + hi) >> 1;
        if (a[mid] < key) lo = mid + 1; else hi = mid;
    }
    return lo;
}

__global__ void __launch_bounds__(128) k_poolmlp(const int* __restrict__ n2g,
                                                 const float* __restrict__ W1,
                                                 const float* __restrict__ b1,
                                                 const float* __restrict__ W2,
                                                 const float* __restrict__ b2,
                                                 float* __restrict__ out) {
    __shared__ int range[2];
    __shared__ float gs[DIM], ts[DIM];
    int gid = blockIdx.x, t = threadIdx.x;
    if (t < 2) range[t] = lbound(n2g, NN, gid + t);
    __syncthreads();
    int s = range[0], e = range[1];

    float sc = g_bnp[t], sh = g_bnp[DIM + t];
    float sum = 0.f;
    for (int n = s; n < e; n++)
        sum += fmaxf(fmaf(g_y[(size_t)n * DIM + t], sc, sh), 0.f);
    float cnt = fmaxf((float)(e - s), 1.0f);
    gs[t] = sum / cnt;
    __syncthreads();

    float acc = b1[t];
#pragma unroll 4
    for (int k = 0; k < DIM; k++) acc = fmaf(gs[k], W1[k * DIM + t], acc);
    ts[t] = fmaxf(acc, 0.f);
    __syncthreads();
    float acc2 = b2[t];
#pragma unroll 4
    for (int k = 0; k < DIM; k++) acc2 = fmaf(ts[k], W2[k * DIM + t], acc2);
    out[gid * DIM + t] = acc2;
}

// ---------------- launcher ----------------
extern "C" void kernel_launch(void* const* d_in, const int* in_sizes, int n_in,
                              void* d_out, int out_size) {
    const int*   nfeat    = (const int*)d_in[0];
    const int*   efeat    = (const int*)d_in[1];
    const int*   src      = (const int*)d_in[2];
    const int*   dst      = (const int*)d_in[3];
    const int*   n2g      = (const int*)d_in[4];
    const float* atom_emb = (const float*)d_in[5];
    const float* edge_emb = (const float*)d_in[6];
    const float* W        = (const float*)d_in[7];
    const float* b        = (const float*)d_in[8];
    const float* gamma    = (const float*)d_in[9];
    const float* beta     = (const float*)d_in[10];
    const float* W1       = (const float*)d_in[11];
    const float* b1       = (const float*)d_in[12];
    const float* W2       = (const float*)d_in[13];
    const float* b2       = (const float*)d_in[14];
    float* out = (float*)d_out;

    static bool attr_set = false;
    if (!attr_set) {
        cudaFuncSetAttribute(k_gemm, cudaFuncAttributeMaxDynamicSharedMemorySize,
                             SM_TOTAL);
        attr_set = true;
    }

    const int nthr = 256;
    int gNode32 = (NN * 32 + nthr - 1) / nthr;
    int gEdge   = (NE + nthr - 1) / nthr;
    int gNode   = (NN + nthr - 1) / nthr;

    k_init<<<gNode32, nthr>>>(nfeat, atom_emb);
    k_hist<<<gEdge, nthr>>>(dst);
    k_wconv<<<NL, 128>>>(W);
    k_scan1<<<NBLK, 256>>>();
    k_scan2<<<1, 1024>>>();
    k_scan3<<<gNode, nthr>>>();
    k_fill<<<gEdge, nthr>>>(src, dst, efeat);

    for (int l = 0; l < NL; l++) {
        if (l == 0)
            k_aggregate<false><<<(NN + 7) / 8, 256>>>(edge_emb);
        else
            k_aggregate<true><<<(NN + 7) / 8, 256>>>(edge_emb + (size_t)l * BONDV * DIM);
        k_gemm<<<NTILE, 256, SM_TOTAL>>>(l, b + (size_t)l * DIM);
        k_bnstat<<<1, 128>>>(gamma + (size_t)l * DIM, beta + (size_t)l * DIM);
    }

    k_poolmlp<<<NG, 128>>>(n2g, W1, b1, W2, b2, out);
}